// round 8
// baseline (speedup 1.0000x reference)
#include <cuda_runtime.h>
#include <cstdint>

typedef unsigned long long ull;

#define BS    8
#define NPTS  1024
#define JJ    3
#define KIN   96
#define FOUT  64
#define ROWS  (BS*NPTS)      // 8192
#define MC    32             // m per chunk
#define NCH   (NPTS/MC)      // 32
#define MT    64             // n rows per block
#define NT1   (NPTS/MT)      // 16
#define NBLK1 (NT1*BS)       // 128
#define ATB   8192           // A tile bytes (64 rows x 128B)
#define BTB   4096           // B tile bytes (32 rows x 128B)
#define PYT   68             // yT pitch (floats)

__device__ __align__(16) float g_wt[KIN*FOUT];
__device__ float g_psum[NBLK1*FOUT];
__device__ float g_psq [NBLK1*FOUT];
__device__ float g_coef[2*FOUT];
__device__ int   g_ctr = 0;

// ---------------- helpers ----------------
#define SW128(o) ((o) ^ (((o) >> 3) & 0x70))

__device__ __forceinline__ uint32_t smem_u32(const void* p) {
    uint32_t a;
    asm("{ .reg .u64 t; cvta.to.shared.u64 t, %1; cvt.u32.u64 %0, t; }" : "=r"(a) : "l"(p));
    return a;
}
__device__ __forceinline__ uint32_t cvt2(float f0, float f1) {   // lo=f0, hi=f1
    uint32_t r;
    asm("cvt.rn.bf16x2.f32 %0, %1, %2;" : "=r"(r) : "f"(f1), "f"(f0));
    return r;
}
__device__ __forceinline__ void sts32(uint32_t a, uint32_t v) {
    asm volatile("st.shared.b32 [%0], %1;" :: "r"(a), "r"(v) : "memory");
}
__device__ __forceinline__ void sts128(uint32_t a, uint32_t v0, uint32_t v1,
                                       uint32_t v2, uint32_t v3) {
    asm volatile("st.shared.v4.b32 [%0], {%1,%2,%3,%4};"
                 :: "r"(a), "r"(v0), "r"(v1), "r"(v2), "r"(v3) : "memory");
}
__device__ __forceinline__ void ldmx4(uint32_t* r, uint32_t a) {
    asm volatile("ldmatrix.sync.aligned.m8n8.x4.shared.b16 {%0,%1,%2,%3}, [%4];"
                 : "=r"(r[0]), "=r"(r[1]), "=r"(r[2]), "=r"(r[3]) : "r"(a));
}
__device__ __forceinline__ void mma16816(float* d, const uint32_t* A, const uint32_t* B) {
    asm volatile(
        "mma.sync.aligned.m16n8k16.row.col.f32.bf16.bf16.f32 "
        "{%0,%1,%2,%3}, {%4,%5,%6,%7}, {%8,%9}, {%0,%1,%2,%3};"
        : "+f"(d[0]), "+f"(d[1]), "+f"(d[2]), "+f"(d[3])
        : "r"(A[0]), "r"(A[1]), "r"(A[2]), "r"(A[3]), "r"(B[0]), "r"(B[1]));
}
__device__ __forceinline__ ull fma2(ull a, ull b, ull c) {
    ull d;
    asm("fma.rn.f32x2 %0, %1, %2, %3;" : "=l"(d) : "l"(a), "l"(b), "l"(c));
    return d;
}
__device__ __forceinline__ ull dup2(float x) {
    unsigned b = __float_as_uint(x);
    return (((ull)b) << 32) | (ull)b;
}

// ---------------- K0: fuse/transpose weights ----------------
__global__ void k0_wt(const float* __restrict__ W1, const float* __restrict__ W2) {
    int t = blockIdx.x * 256 + threadIdx.x;
    if (t < KIN * FOUT) {
        int c = t & 63, k = t >> 6;
        g_wt[k * FOUT + c] = (c < 32) ? W1[c * KIN + k] : W2[(c - 32) * KIN + k];
    }
}

// ---------------- K1 fused: bf16-split GMul (mma.sync) + MLP + BN partials ----------------
// 256 threads = 8 warps. Warp (w&3) -> 16-row band, (w>>2) -> 16-f half.
__global__ __launch_bounds__(256) void k1_fused(const float* __restrict__ WW,
                                                const float* __restrict__ X,
                                                const float* __restrict__ b1,
                                                const float* __restrict__ b2,
                                                float* __restrict__ Z) {
    __shared__ float4 smv[(3*ATB + BTB) / 16];   // tiles; later overlaid by yT
    __shared__ float ps[4*FOUT], pq[4*FOUT];
    __shared__ float rs[4*FOUT], rq[4*FOUT];
    __shared__ int last_s;

    const uint32_t sb = smem_u32(smv);
    const uint32_t Bb = sb + 3*ATB;

    const int t = threadIdx.x, warp = t >> 5, lane = t & 31;
    const int b  = blockIdx.y;
    const int n0 = blockIdx.x * MT;

    const float* wwC = WW + (size_t)(b * NPTS + n0) * (NPTS * 3);
    const float* xC  = X + (size_t)b * NPTS * 32;

    // WW loader: thread -> (n-row ln, 8-m group mq); 24 consecutive floats
    const int ln = t >> 2, mq = t & 3;
    const float* wrow = wwC + (size_t)ln * (NPTS * 3) + mq * 24;
    // X loader (t<128): m-pair mp, 4 f at xf0
    const int mp = t >> 3, xf0 = (t & 7) * 4;
    const float* xrow = xC + 2 * mp * 32 + xf0;

    // fragment offsets
    const int rw = (warp & 3) * 16;
    const int fh = warp >> 2;
    const uint32_t aoffL = (uint32_t)(rw + (lane & 15)) * 128 + (lane >> 4) * 16;
    const uint32_t boffL = (uint32_t)(8 * (lane >> 4) + (lane & 7)) * 128
                         + ((lane >> 3) & 1) * 16 + (uint32_t)fh * 2048;

    float acc[24];   // [j][fbl][4]
#pragma unroll
    for (int i = 0; i < 24; i++) acc[i] = 0.f;

    // prologue
    float wf[24];
    float4 xr0, xr1;
#pragma unroll
    for (int i = 0; i < 6; i++)
        *(float4*)(wf + 4*i) = *(const float4*)(wrow + 4*i);
    if (t < 128) {
        xr0 = *(const float4*)(xrow);
        xr1 = *(const float4*)(xrow + 32);
    }

    for (int c = 0; c < NCH; ++c) {
        // ---- stage A tiles (hi|lo bf16, SW128) ----
#pragma unroll
        for (int j = 0; j < 3; j++) {
            uint32_t hw[4], lw[4];
#pragma unroll
            for (int p = 0; p < 4; p++) {
                float a0 = wf[(2*p)   * 3 + j];
                float a1 = wf[(2*p+1) * 3 + j];
                uint32_t h = cvt2(a0, a1);
                float r0 = a0 - __uint_as_float(h << 16);
                float r1 = a1 - __uint_as_float(h & 0xffff0000u);
                hw[p] = h;
                lw[p] = cvt2(r0, r1);
            }
            const uint32_t tb = sb + j * ATB;
            const uint32_t rb = (uint32_t)ln * 128 + mq * 16;
            sts128(tb + SW128(rb),      hw[0], hw[1], hw[2], hw[3]);
            sts128(tb + SW128(rb + 64), lw[0], lw[1], lw[2], lw[3]);
        }
        // ---- stage B tile ----
        if (t < 128) {
            float xa[4] = { xr0.x, xr0.y, xr0.z, xr0.w };
            float xb[4] = { xr1.x, xr1.y, xr1.z, xr1.w };
#pragma unroll
            for (int ff = 0; ff < 4; ff++) {
                uint32_t h = cvt2(xa[ff], xb[ff]);
                float r0 = xa[ff] - __uint_as_float(h << 16);
                float r1 = xb[ff] - __uint_as_float(h & 0xffff0000u);
                uint32_t l = cvt2(r0, r1);
                uint32_t fr = (uint32_t)(xf0 + ff) * 128 + 4 * mp;
                sts32(Bb + SW128(fr),      h);
                sts32(Bb + SW128(fr + 64), l);
            }
        }
        __syncthreads();

        // ---- prefetch next chunk ----
        if (c + 1 < NCH) {
            const float* wp = wrow + (c + 1) * (MC * 3);
#pragma unroll
            for (int i = 0; i < 6; i++)
                *(float4*)(wf + 4*i) = *(const float4*)(wp + 4*i);
            if (t < 128) {
                const float* xp = xrow + (c + 1) * (MC * 32);
                xr0 = *(const float4*)(xp);
                xr1 = *(const float4*)(xp + 32);
            }
        }

        // ---- mma: 3 passes (AhBh, AhBl, AlBh) ----
#pragma unroll
        for (int ks = 0; ks < 2; ks++) {
            uint32_t Bh[4], Bl[4];
            ldmx4(Bh, Bb + SW128(boffL + ks*32));
            ldmx4(Bl, Bb + SW128(boffL + 64 + ks*32));
#pragma unroll
            for (int j = 0; j < 3; j++) {
                uint32_t Ah[4], Al[4];
                const uint32_t ab = sb + j * ATB;
                ldmx4(Ah, ab + SW128(aoffL + ks*32));
                ldmx4(Al, ab + SW128(aoffL + 64 + ks*32));
#pragma unroll
                for (int fbl = 0; fbl < 2; fbl++) {
                    float* d = acc + j*8 + fbl*4;
                    mma16816(d, Ah, Bh + 2*fbl);
                    mma16816(d, Ah, Bl + 2*fbl);
                    mma16816(d, Al, Bh + 2*fbl);
                }
            }
        }
        __syncthreads();
    }

    // ---- stage y transposed into smem (overlay tiles) ----
    float* yT = (float*)smv;
    const int g = lane >> 2, tq = lane & 3;
    const int r0 = rw + g, r1 = rw + 8 + g;
#pragma unroll
    for (int j = 0; j < 3; j++)
#pragma unroll
        for (int fbl = 0; fbl < 2; fbl++) {
            const float* d = acc + j*8 + fbl*4;
            const int cb = j*32 + (fh*2 + fbl)*8 + 2*tq;
            yT[cb*PYT + r0]     = d[0];
            yT[(cb+1)*PYT + r0] = d[1];
            yT[cb*PYT + r1]     = d[2];
            yT[(cb+1)*PYT + r1] = d[3];
        }
    __syncthreads();

    // ---- MLP + BN partials: col = t&63, rg = t>>6 (4 groups x 16 rows) ----
    const int col = t & 63, rg = t >> 6;
    const int rbase = rg * 16;
    ull acc2[8];
#pragma unroll
    for (int q = 0; q < 8; q++) acc2[q] = 0ULL;

#pragma unroll 4
    for (int k = 0; k < KIN; k++) {
        ull wd = dup2(__ldg(&g_wt[k * FOUT + col]));
        const float* yp = yT + k * PYT + rbase;
#pragma unroll
        for (int q = 0; q < 4; q++) {
            ulonglong2 yv = *(const ulonglong2*)(yp + 4*q);
            acc2[2*q]     = fma2(yv.x, wd, acc2[2*q]);
            acc2[2*q + 1] = fma2(yv.y, wd, acc2[2*q + 1]);
        }
    }

    const float bias = (col < 32) ? __ldg(&b1[col]) : __ldg(&b2[col - 32]);
    const size_t grow = (size_t)(b * NPTS + n0) + rbase;
    float s = 0.f, sq = 0.f;
#pragma unroll
    for (int q = 0; q < 8; q++) {
        union { ull u; float f[2]; } cv; cv.u = acc2[q];
#pragma unroll
        for (int h = 0; h < 2; h++) {
            float z = cv.f[h] + bias;
            if (col < 32) z = fmaxf(z, 0.f);
            Z[(grow + 2*q + h) * FOUT + col] = z;
            s += z; sq += z * z;
        }
    }
    ps[rg * FOUT + col] = s; pq[rg * FOUT + col] = sq;
    __syncthreads();

    const int blk = blockIdx.y * NT1 + blockIdx.x;
    if (rg == 0) {   // fixed order: deterministic
        float S = (ps[col] + ps[FOUT + col]) + (ps[2*FOUT + col] + ps[3*FOUT + col]);
        float Q = (pq[col] + pq[FOUT + col]) + (pq[2*FOUT + col] + pq[3*FOUT + col]);
        g_psum[blk * FOUT + col] = S;
        g_psq [blk * FOUT + col] = Q;
    }

    // ---- last block computes BN coefficients ----
    __threadfence();
    if (t == 0) last_s = (atomicAdd(&g_ctr, 1) == NBLK1 - 1);
    __syncthreads();
    if (last_s) {
        const int h = t >> 6;   // 4 segments x 32 blocks
        float S = 0.f, Q = 0.f;
#pragma unroll 4
        for (int i = 0; i < NBLK1/4; i++) {
            int idx = (h * (NBLK1/4) + i) * FOUT + col;
            S += g_psum[idx];
            Q += g_psq [idx];
        }
        rs[h * FOUT + col] = S; rq[h * FOUT + col] = Q;
        __syncthreads();
        if (t < FOUT) {
            float Sf = (rs[t] + rs[FOUT + t]) + (rs[2*FOUT + t] + rs[3*FOUT + t]);
            float Qf = (rq[t] + rq[FOUT + t]) + (rq[2*FOUT + t] + rq[3*FOUT + t]);
            float mean = Sf * (1.0f / ROWS);
            float var  = Qf * (1.0f / ROWS) - mean * mean;
            float sc   = rsqrtf(var + 1e-5f);   // gamma applied in k4 via g_coef
            g_coef[t]        = sc;
            g_coef[FOUT + t] = -mean * sc;
        }
        if (t == 0) g_ctr = 0;   // reset for next replay
    }
}

// ---------------- K4: in-place normalize (applies gamma/beta) ----------------
__global__ __launch_bounds__(256) void k4_norm(float* __restrict__ Z,
                                               const float* __restrict__ gamma,
                                               const float* __restrict__ beta) {
    int i0 = blockIdx.x * 512 + threadIdx.x;
    float4* Z4 = (float4*)Z;
    float4 v0 = Z4[i0];
    float4 v1 = Z4[i0 + 256];
    int c = (i0 & 15) * 4;
    float g0 = __ldg(&gamma[c]),   g1 = __ldg(&gamma[c+1]);
    float g2 = __ldg(&gamma[c+2]), g3 = __ldg(&gamma[c+3]);
    float s0 = g_coef[c]   * g0, s1 = g_coef[c+1] * g1;
    float s2 = g_coef[c+2] * g2, s3 = g_coef[c+3] * g3;
    float h0 = g_coef[FOUT+c]   * g0 + __ldg(&beta[c]);
    float h1 = g_coef[FOUT+c+1] * g1 + __ldg(&beta[c+1]);
    float h2 = g_coef[FOUT+c+2] * g2 + __ldg(&beta[c+2]);
    float h3 = g_coef[FOUT+c+3] * g3 + __ldg(&beta[c+3]);
    v0.x = v0.x*s0 + h0; v0.y = v0.y*s1 + h1; v0.z = v0.z*s2 + h2; v0.w = v0.w*s3 + h3;
    v1.x = v1.x*s0 + h0; v1.y = v1.y*s1 + h1; v1.z = v1.z*s2 + h2; v1.w = v1.w*s3 + h3;
    Z4[i0] = v0;
    Z4[i0 + 256] = v1;
}

extern "C" void kernel_launch(void* const* d_in, const int* in_sizes, int n_in,
                              void* d_out, int out_size) {
    const float* WW    = (const float*)d_in[0];
    const float* X     = (const float*)d_in[1];
    const float* W1    = (const float*)d_in[2];
    const float* b1    = (const float*)d_in[3];
    const float* W2    = (const float*)d_in[4];
    const float* b2    = (const float*)d_in[5];
    const float* gamma = (const float*)d_in[6];
    const float* beta  = (const float*)d_in[7];
    float* Z = (float*)d_out;

    k0_wt<<<(KIN * FOUT + 255) / 256, 256>>>(W1, W2);
    dim3 g1(NT1, BS);
    k1_fused<<<g1, 256>>>(WW, X, b1, b2, Z);
    k4_norm<<<(ROWS * FOUT / 4) / 512, 256>>>(Z, gamma, beta);
}